// round 11
// baseline (speedup 1.0000x reference)
#include <cuda_runtime.h>
#include <cuda_bf16.h>
#include <math.h>

// Shapes (fixed): B=2, T=512, D=256, H=8, c=32
#define NTOK 1024
#define DM   256
#define NH   8
#define HC   32
#define T    512
#define KSPLIT 8

__device__ float g_qkv [NTOK * 3 * DM];          // 1024 x 768
__device__ float g_x1  [NTOK * DM];              // 1024 x 256
__device__ float g_h   [NTOK * 4 * DM];          // 1024 x 1024
__device__ float g_part[KSPLIT * NTOK * DM];     // split-K partials

__device__ __forceinline__ void cp16(void* smem_dst, const void* gsrc) {
    unsigned s = (unsigned)__cvta_generic_to_shared(smem_dst);
    asm volatile("cp.async.cg.shared.global [%0], [%1], 16;\n" :: "r"(s), "l"(gsrc));
}

// packed f32x2 helpers (sm_100+)
__device__ __forceinline__ unsigned long long addx2(unsigned long long a, unsigned long long b) {
    unsigned long long d;
    asm("add.rn.f32x2 %0, %1, %2;" : "=l"(d) : "l"(a), "l"(b));
    return d;
}
__device__ __forceinline__ unsigned long long fmax2(unsigned long long a, unsigned long long b,
                                                    unsigned long long c) {
    unsigned long long d;
    asm("fma.rn.f32x2 %0, %1, %2, %3;" : "=l"(d) : "l"(a), "l"(b), "l"(c));
    return d;
}
__device__ __forceinline__ unsigned long long pack2(float lo, float hi) {
    unsigned long long d;
    asm("mov.b64 %0, {%1, %2};" : "=l"(d) : "f"(lo), "f"(hi));
    return d;
}
__device__ __forceinline__ void unpack2(unsigned long long v, float& lo, float& hi) {
    asm("mov.b64 {%0, %1}, %2;" : "=f"(lo), "=f"(hi) : "l"(v));
}

// ---------------------------------------------------------------------------
// TF32 tensor-core GEMM, 3-stage cp.async pipeline, split-K via blockIdx.z.
// BM=64, BN=64, BK=32, 256 threads, warp tile 32x16. PDL: weight tiles are
// prefetched before cudaGridDependencySynchronize().
// ---------------------------------------------------------------------------
template<int ACT, bool RES, bool RAW, bool DEP>
__global__ void gemm_tc(const float* __restrict__ A, const float* __restrict__ B,
                        const float* __restrict__ bias, const float* __restrict__ res,
                        float* __restrict__ C, int M, int N, int Klen, int lda)
{
    __shared__ float As[3][64 * 36];
    __shared__ float Bs[3][32 * 68];

    const int tid  = threadIdx.x;
    const int w    = tid >> 5;
    const int lane = tid & 31;
    const int g    = lane >> 2;
    const int tg   = lane & 3;
    const int warpM = w >> 2;
    const int warpN = w & 3;

    const int row0 = blockIdx.y * 64;
    const int col0 = blockIdx.x * 64;

    const int kz = blockIdx.z * Klen;
    A += kz;
    B += (size_t)kz * N;
    if (RAW) C += (size_t)blockIdx.z * M * N;

    float acc[2][2][4] = {};

    auto loadA = [&](int k0, int buf) {
        #pragma unroll
        for (int c = tid; c < 512; c += 256) {
            int rA = c >> 3, cA = (c & 7) * 4;
            cp16(&As[buf][rA * 36 + cA], A + (size_t)(row0 + rA) * lda + k0 + cA);
        }
    };
    auto loadB = [&](int k0, int buf) {
        #pragma unroll
        for (int c = tid; c < 512; c += 256) {
            int rB = c >> 4, cB = (c & 15) * 4;
            cp16(&Bs[buf][rB * 68 + cB], B + (size_t)(k0 + rB) * N + col0 + cB);
        }
    };

    const int nt = Klen >> 5;

    loadB(0, 0);
    if (nt > 1) loadB(32, 1);
    if (DEP) cudaGridDependencySynchronize();
    loadA(0, 0);
    asm volatile("cp.async.commit_group;\n");
    if (nt > 1) {
        loadA(32, 1);
        asm volatile("cp.async.commit_group;\n");
    }

    for (int i = 0; i < nt; i++) {
        if (i + 2 < nt) {
            loadB((i + 2) << 5, (i + 2) % 3);
            loadA((i + 2) << 5, (i + 2) % 3);
            asm volatile("cp.async.commit_group;\n");
            asm volatile("cp.async.wait_group 2;\n");
        } else if (i + 1 < nt) {
            asm volatile("cp.async.wait_group 1;\n");
        } else {
            asm volatile("cp.async.wait_group 0;\n");
        }
        __syncthreads();

        const float* Ab = As[i % 3];
        const float* Bb = Bs[i % 3];

        #pragma unroll
        for (int ks = 0; ks < 4; ks++) {
            const int kk = ks * 8;
            unsigned a[2][4], b[2][2];
            #pragma unroll
            for (int ii = 0; ii < 2; ii++) {
                const int rb = warpM * 32 + ii * 16;
                a[ii][0] = __float_as_uint(Ab[(rb + g    ) * 36 + kk + tg    ]);
                a[ii][1] = __float_as_uint(Ab[(rb + g + 8) * 36 + kk + tg    ]);
                a[ii][2] = __float_as_uint(Ab[(rb + g    ) * 36 + kk + tg + 4]);
                a[ii][3] = __float_as_uint(Ab[(rb + g + 8) * 36 + kk + tg + 4]);
            }
            #pragma unroll
            for (int j = 0; j < 2; j++) {
                const int cb = warpN * 16 + j * 8;
                b[j][0] = __float_as_uint(Bb[(kk + tg    ) * 68 + cb + g]);
                b[j][1] = __float_as_uint(Bb[(kk + tg + 4) * 68 + cb + g]);
            }
            #pragma unroll
            for (int ii = 0; ii < 2; ii++)
                #pragma unroll
                for (int j = 0; j < 2; j++) {
                    asm volatile(
                        "mma.sync.aligned.m16n8k8.row.col.f32.tf32.tf32.f32 "
                        "{%0,%1,%2,%3}, {%4,%5,%6,%7}, {%8,%9}, {%0,%1,%2,%3};"
                        : "+f"(acc[ii][j][0]), "+f"(acc[ii][j][1]),
                          "+f"(acc[ii][j][2]), "+f"(acc[ii][j][3])
                        : "r"(a[ii][0]), "r"(a[ii][1]), "r"(a[ii][2]), "r"(a[ii][3]),
                          "r"(b[j][0]), "r"(b[j][1]));
                }
        }
        __syncthreads();
    }

    #pragma unroll
    for (int ii = 0; ii < 2; ii++) {
        const int rb = row0 + warpM * 32 + ii * 16;
        #pragma unroll
        for (int j = 0; j < 2; j++) {
            const int cb = col0 + warpN * 16 + j * 8;
            #pragma unroll
            for (int rg = 0; rg < 2; rg++) {
                const int r = rb + g + rg * 8;
                const int c = cb + tg * 2;
                float v0 = acc[ii][j][rg * 2 + 0];
                float v1 = acc[ii][j][rg * 2 + 1];
                if (!RAW) {
                    v0 += bias[c];
                    v1 += bias[c + 1];
                    if (ACT == 1) {
                        v0 = v0 * __fdividef(1.f, 1.f + __expf(-1.702f * v0));
                        v1 = v1 * __fdividef(1.f, 1.f + __expf(-1.702f * v1));
                    }
                    if (RES) {
                        float2 rv = *(const float2*)&res[(size_t)r * N + c];
                        v0 += rv.x; v1 += rv.y;
                    }
                }
                float2 o; o.x = v0; o.y = v1;
                *(float2*)&C[(size_t)r * N + c] = o;
            }
        }
    }
    cudaTriggerProgrammaticLaunchCompletion();   // after stores
}

// Split-K reduce for proj: out = sum_8(part) + bias + res.
__global__ void reduce_proj(const float* __restrict__ part, const float* __restrict__ bias,
                            const float* __restrict__ res, float* __restrict__ out)
{
    cudaGridDependencySynchronize();
    const int i = blockIdx.x * 256 + threadIdx.x;      // 65536 float4
    const float4* p = (const float4*)part;
    float4 bv = ((const float4*)bias)[i & 63];
    float4 rv = ((const float4*)res)[i];
    float sx = bv.x + rv.x, sy = bv.y + rv.y, sz = bv.z + rv.z, sw = bv.w + rv.w;
    #pragma unroll
    for (int z = 0; z < KSPLIT; z++) {
        float4 s = p[i + z * 65536];
        sx += s.x; sy += s.y; sz += s.z; sw += s.w;
    }
    float4 o; o.x = sx; o.y = sy; o.z = sz; o.w = sw;
    ((float4*)out)[i] = o;
}

// ---------------------------------------------------------------------------
// L1-distance attention + residual, packed f32x2 math, direct exp.
// 128 blocks x 512 threads (16 warps). Warp w: qg=w&1, ss=w>>1 (8 key-splits).
// Key loop unrolled x2: two independent keys in flight -> 4 distance chains,
// halving exposed FADD2 dependency latency.
// ---------------------------------------------------------------------------
__global__ void attn_kernel(const float* __restrict__ x, const float* __restrict__ qkv,
                            float* __restrict__ x1)
{
    extern __shared__ float sh[];
    float* Ksh = sh;
    float* Vsh = sh + 16384;

    const int bid = blockIdx.x;
    const int bh  = bid >> 3;
    const int qb  = bid & 7;
    const int b   = bh >> 3;
    const int hh  = bh & 7;
    const int tid = threadIdx.x;
    const int w   = tid >> 5;
    const int lane = tid & 31;
    const int t0  = qb * 64;

    const float* qkv_bh = qkv + (size_t)b * T * 768 + hh * 96;

    cudaGridDependencySynchronize();   // qkv must be complete

    for (int i = tid; i < T * 8; i += 512) {
        int s = i >> 3, j = i & 7;
        uint4 kv = ((const uint4*)(qkv_bh + (size_t)s * 768 + 32))[j];
        kv.x ^= 0x80000000u; kv.y ^= 0x80000000u;
        kv.z ^= 0x80000000u; kv.w ^= 0x80000000u;
        ((uint4*)Ksh)[i] = kv;
        ((float4*)Vsh)[i] = ((const float4*)(qkv_bh + (size_t)s * 768 + 64))[j];
    }

    const int qg   = w & 1;
    const int ss   = w >> 1;
    const int qidx = qg * 32 + lane;
    const int t    = t0 + qidx;

    unsigned long long q2[16];
    {
        const ulonglong2* qsrc = (const ulonglong2*)(qkv_bh + (size_t)t * 768);
        #pragma unroll
        for (int j = 0; j < 8; j++) {
            ulonglong2 v = qsrc[j];
            q2[2 * j] = v.x; q2[2 * j + 1] = v.y;
        }
    }
    __syncthreads();

    const float scale = 0.1767766952966369f;
    const unsigned long long ABSM = 0x7FFFFFFF7FFFFFFFULL;
    float l = 0.f;
    unsigned long long o2[16];
    #pragma unroll
    for (int j = 0; j < 16; j++) o2[j] = 0ULL;

    const int s_begin = ss * 64;
    #pragma unroll 1
    for (int s = s_begin; s < s_begin + 64; s += 2) {
        const ulonglong2* krow0 = (const ulonglong2*)(Ksh + s * 32);
        const ulonglong2* krow1 = (const ulonglong2*)(Ksh + (s + 1) * 32);
        unsigned long long accA0 = 0ULL, accB0 = 0ULL;
        unsigned long long accA1 = 0ULL, accB1 = 0ULL;
        #pragma unroll
        for (int j = 0; j < 8; j++) {
            ulonglong2 k0 = krow0[j];
            ulonglong2 k1 = krow1[j];
            unsigned long long d00 = addx2(q2[2 * j],     k0.x) & ABSM;
            unsigned long long d01 = addx2(q2[2 * j + 1], k0.y) & ABSM;
            unsigned long long d10 = addx2(q2[2 * j],     k1.x) & ABSM;
            unsigned long long d11 = addx2(q2[2 * j + 1], k1.y) & ABSM;
            accA0 = addx2(accA0, d00);
            accB0 = addx2(accB0, d01);
            accA1 = addx2(accA1, d10);
            accB1 = addx2(accB1, d11);
        }
        float a00, a01, b00, b01, a10, a11, b10, b11;
        unpack2(accA0, a00, a01);
        unpack2(accB0, b00, b01);
        unpack2(accA1, a10, a11);
        unpack2(accB1, b10, b11);
        float dist0 = (a00 + a01) + (b00 + b01);
        float dist1 = (a10 + a11) + (b10 + b11);
        float wgt0 = (s     == t) ? 0.f : __fdividef(1.f, 0.001f + dist0 * scale);
        float wgt1 = (s + 1 == t) ? 0.f : __fdividef(1.f, 0.001f + dist1 * scale);
        float p0 = __expf(wgt0);             // direct exp: wgt in [0, ~1.5]
        float p1 = __expf(wgt1);
        l += p0 + p1;
        unsigned long long pp0 = pack2(p0, p0);
        unsigned long long pp1 = pack2(p1, p1);
        const ulonglong2* vrow0 = (const ulonglong2*)(Vsh + s * 32);
        const ulonglong2* vrow1 = (const ulonglong2*)(Vsh + (s + 1) * 32);
        #pragma unroll
        for (int j = 0; j < 8; j++) {
            ulonglong2 v0 = vrow0[j];
            ulonglong2 v1 = vrow1[j];
            o2[2 * j]     = fmax2(pp0, v0.x, o2[2 * j]);
            o2[2 * j + 1] = fmax2(pp0, v0.y, o2[2 * j + 1]);
            o2[2 * j]     = fmax2(pp1, v1.x, o2[2 * j]);
            o2[2 * j + 1] = fmax2(pp1, v1.y, o2[2 * j + 1]);
        }
    }
    __syncthreads();

    // Merge: plain sums (no rescaling needed without online max).
    unsigned long long* obuf64 = (unsigned long long*)sh;   // [8][64][17] u64
    float* obuf  = sh;                      // stride 34 floats per (ss,q) row
    float* lbuf  = sh + 17408;              // [64][8]
    float* Linv  = sh + 17408 + 512;        // [64]

    unsigned long long* od = obuf64 + (ss * 64 + qidx) * 17;
    #pragma unroll
    for (int j = 0; j < 16; j++) od[j] = o2[j];
    lbuf[qidx * 8 + ss] = l;
    __syncthreads();

    if (tid < 64) {
        float L = 0.f;
        #pragma unroll
        for (int i = 0; i < 8; i++) L += lbuf[tid * 8 + i];
        Linv[tid] = __fdividef(1.f, L);
    }
    __syncthreads();

    for (int e = tid; e < 64 * 32; e += 512) {
        int qi = e >> 5, c = e & 31;
        float sum = 0.f;
        #pragma unroll
        for (int p = 0; p < 8; p++)
            sum += obuf[(p * 64 + qi) * 34 + c];
        float outv = sum * Linv[qi];
        size_t idx = ((size_t)b * T + (t0 + qi)) * DM + hh * HC + c;
        x1[idx] = x[idx] + outv;
    }
    cudaTriggerProgrammaticLaunchCompletion();   // after stores
}

// ---------------------------------------------------------------------------
template<typename K, typename... Args>
static void launch_pdl(K kernel, dim3 grid, dim3 block, unsigned smem, Args... args)
{
    cudaLaunchAttribute attr[1];
    attr[0].id = cudaLaunchAttributeProgrammaticStreamSerialization;
    attr[0].val.programmaticStreamSerializationAllowed = 1;
    cudaLaunchConfig_t cfg{};
    cfg.gridDim = grid;
    cfg.blockDim = block;
    cfg.dynamicSmemBytes = smem;
    cfg.stream = 0;
    cfg.attrs = attr;
    cfg.numAttrs = 1;
    cudaLaunchKernelEx(&cfg, kernel, args...);
}

extern "C" void kernel_launch(void* const* d_in, const int* in_sizes, int n_in,
                              void* d_out, int out_size)
{
    const float* x      = (const float*)d_in[0];
    const float* W_qkv  = (const float*)d_in[1];
    const float* b_qkv  = (const float*)d_in[2];
    const float* W_fc   = (const float*)d_in[3];
    const float* b_fc   = (const float*)d_in[4];
    const float* W_proj = (const float*)d_in[5];
    const float* b_proj = (const float*)d_in[6];
    float* out = (float*)d_out;

    float *p_qkv, *p_x1, *p_h, *p_part;
    cudaGetSymbolAddress((void**)&p_qkv,  g_qkv);
    cudaGetSymbolAddress((void**)&p_x1,   g_x1);
    cudaGetSymbolAddress((void**)&p_h,    g_h);
    cudaGetSymbolAddress((void**)&p_part, g_part);

    static bool cfgd = false;
    if (!cfgd) {
        cudaFuncSetAttribute(attn_kernel, cudaFuncAttributeMaxDynamicSharedMemorySize, 131072);
        cfgd = true;
    }

    // 1) qkv = x @ W_qkv + b_qkv            (1024 x 768, K=256) grid 192
    launch_pdl(gemm_tc<0, false, false, false>, dim3(12, 16), dim3(256), 0,
               x, W_qkv, b_qkv, (const float*)nullptr, p_qkv, NTOK, 3 * DM, DM, DM);

    // 2) x1 = x + attention(qkv)
    launch_pdl(attn_kernel, dim3(128), dim3(512), 131072, x, p_qkv, p_x1);

    // 3) h = quick_gelu(x1 @ W_fc + b_fc)   (1024 x 1024, K=256) grid 256
    launch_pdl(gemm_tc<1, false, false, true>, dim3(16, 16), dim3(256), 0,
               p_x1, W_fc, b_fc, (const float*)nullptr, p_h, NTOK, 4 * DM, DM, DM);

    // 4) proj split-K x8 in ONE launch      (1024 x 256, Ksplit=128) grid 512
    launch_pdl(gemm_tc<0, false, true, true>, dim3(4, 16, KSPLIT), dim3(256), 0,
               p_h, W_proj, (const float*)nullptr, (const float*)nullptr,
               p_part, NTOK, DM, 1024 / KSPLIT, 4 * DM);

    // 5) out = sum(partials) + b_proj + x1
    launch_pdl(reduce_proj, dim3(256), dim3(256), 0, p_part, b_proj, p_x1, out);
}

// round 13
// speedup vs baseline: 1.0309x; 1.0309x over previous
#include <cuda_runtime.h>
#include <cuda_bf16.h>
#include <math.h>

// Shapes (fixed): B=2, T=512, D=256, H=8, c=32
#define NTOK 1024
#define DM   256
#define NH   8
#define HC   32
#define T    512
#define KSPLIT 8

__device__ float g_qkv [NTOK * 3 * DM];          // 1024 x 768
__device__ float g_x1  [NTOK * DM];              // 1024 x 256
__device__ float g_h   [NTOK * 4 * DM];          // 1024 x 1024
__device__ float g_part[KSPLIT * NTOK * DM];     // split-K partials

__device__ __forceinline__ void cp16(void* smem_dst, const void* gsrc) {
    unsigned s = (unsigned)__cvta_generic_to_shared(smem_dst);
    asm volatile("cp.async.cg.shared.global [%0], [%1], 16;\n" :: "r"(s), "l"(gsrc));
}

// packed f32x2 helpers (sm_100+)
__device__ __forceinline__ unsigned long long addx2(unsigned long long a, unsigned long long b) {
    unsigned long long d;
    asm("add.rn.f32x2 %0, %1, %2;" : "=l"(d) : "l"(a), "l"(b));
    return d;
}
__device__ __forceinline__ void unpack2(unsigned long long v, float& lo, float& hi) {
    asm("mov.b64 {%0, %1}, %2;" : "=f"(lo), "=f"(hi) : "l"(v));
}

// ---------------------------------------------------------------------------
// TF32 tensor-core GEMM, 3-stage cp.async pipeline, split-K via blockIdx.z.
// BM=64, BN=64, BK=32, 256 threads, warp tile 32x16. PDL: weight tiles are
// prefetched before cudaGridDependencySynchronize().
// ---------------------------------------------------------------------------
template<int ACT, bool RES, bool RAW, bool DEP>
__global__ void gemm_tc(const float* __restrict__ A, const float* __restrict__ B,
                        const float* __restrict__ bias, const float* __restrict__ res,
                        float* __restrict__ C, int M, int N, int Klen, int lda)
{
    __shared__ float As[3][64 * 36];
    __shared__ float Bs[3][32 * 68];

    const int tid  = threadIdx.x;
    const int w    = tid >> 5;
    const int lane = tid & 31;
    const int g    = lane >> 2;
    const int tg   = lane & 3;
    const int warpM = w >> 2;
    const int warpN = w & 3;

    const int row0 = blockIdx.y * 64;
    const int col0 = blockIdx.x * 64;

    const int kz = blockIdx.z * Klen;
    A += kz;
    B += (size_t)kz * N;
    if (RAW) C += (size_t)blockIdx.z * M * N;

    float acc[2][2][4] = {};

    auto loadA = [&](int k0, int buf) {
        #pragma unroll
        for (int c = tid; c < 512; c += 256) {
            int rA = c >> 3, cA = (c & 7) * 4;
            cp16(&As[buf][rA * 36 + cA], A + (size_t)(row0 + rA) * lda + k0 + cA);
        }
    };
    auto loadB = [&](int k0, int buf) {
        #pragma unroll
        for (int c = tid; c < 512; c += 256) {
            int rB = c >> 4, cB = (c & 15) * 4;
            cp16(&Bs[buf][rB * 68 + cB], B + (size_t)(k0 + rB) * N + col0 + cB);
        }
    };

    const int nt = Klen >> 5;

    loadB(0, 0);
    if (nt > 1) loadB(32, 1);
    if (DEP) cudaGridDependencySynchronize();
    loadA(0, 0);
    asm volatile("cp.async.commit_group;\n");
    if (nt > 1) {
        loadA(32, 1);
        asm volatile("cp.async.commit_group;\n");
    }

    for (int i = 0; i < nt; i++) {
        if (i + 2 < nt) {
            loadB((i + 2) << 5, (i + 2) % 3);
            loadA((i + 2) << 5, (i + 2) % 3);
            asm volatile("cp.async.commit_group;\n");
            asm volatile("cp.async.wait_group 2;\n");
        } else if (i + 1 < nt) {
            asm volatile("cp.async.wait_group 1;\n");
        } else {
            asm volatile("cp.async.wait_group 0;\n");
        }
        __syncthreads();

        const float* Ab = As[i % 3];
        const float* Bb = Bs[i % 3];

        #pragma unroll
        for (int ks = 0; ks < 4; ks++) {
            const int kk = ks * 8;
            unsigned a[2][4], b[2][2];
            #pragma unroll
            for (int ii = 0; ii < 2; ii++) {
                const int rb = warpM * 32 + ii * 16;
                a[ii][0] = __float_as_uint(Ab[(rb + g    ) * 36 + kk + tg    ]);
                a[ii][1] = __float_as_uint(Ab[(rb + g + 8) * 36 + kk + tg    ]);
                a[ii][2] = __float_as_uint(Ab[(rb + g    ) * 36 + kk + tg + 4]);
                a[ii][3] = __float_as_uint(Ab[(rb + g + 8) * 36 + kk + tg + 4]);
            }
            #pragma unroll
            for (int j = 0; j < 2; j++) {
                const int cb = warpN * 16 + j * 8;
                b[j][0] = __float_as_uint(Bb[(kk + tg    ) * 68 + cb + g]);
                b[j][1] = __float_as_uint(Bb[(kk + tg + 4) * 68 + cb + g]);
            }
            #pragma unroll
            for (int ii = 0; ii < 2; ii++)
                #pragma unroll
                for (int j = 0; j < 2; j++) {
                    asm volatile(
                        "mma.sync.aligned.m16n8k8.row.col.f32.tf32.tf32.f32 "
                        "{%0,%1,%2,%3}, {%4,%5,%6,%7}, {%8,%9}, {%0,%1,%2,%3};"
                        : "+f"(acc[ii][j][0]), "+f"(acc[ii][j][1]),
                          "+f"(acc[ii][j][2]), "+f"(acc[ii][j][3])
                        : "r"(a[ii][0]), "r"(a[ii][1]), "r"(a[ii][2]), "r"(a[ii][3]),
                          "r"(b[j][0]), "r"(b[j][1]));
                }
        }
        __syncthreads();
    }

    #pragma unroll
    for (int ii = 0; ii < 2; ii++) {
        const int rb = row0 + warpM * 32 + ii * 16;
        #pragma unroll
        for (int j = 0; j < 2; j++) {
            const int cb = col0 + warpN * 16 + j * 8;
            #pragma unroll
            for (int rg = 0; rg < 2; rg++) {
                const int r = rb + g + rg * 8;
                const int c = cb + tg * 2;
                float v0 = acc[ii][j][rg * 2 + 0];
                float v1 = acc[ii][j][rg * 2 + 1];
                if (!RAW) {
                    v0 += bias[c];
                    v1 += bias[c + 1];
                    if (ACT == 1) {
                        v0 = v0 * __fdividef(1.f, 1.f + __expf(-1.702f * v0));
                        v1 = v1 * __fdividef(1.f, 1.f + __expf(-1.702f * v1));
                    }
                    if (RES) {
                        float2 rv = *(const float2*)&res[(size_t)r * N + c];
                        v0 += rv.x; v1 += rv.y;
                    }
                }
                float2 o; o.x = v0; o.y = v1;
                *(float2*)&C[(size_t)r * N + c] = o;
            }
        }
    }
    cudaTriggerProgrammaticLaunchCompletion();   // after stores
}

// Split-K reduce for proj: out = sum_8(part) + bias + res.
__global__ void reduce_proj(const float* __restrict__ part, const float* __restrict__ bias,
                            const float* __restrict__ res, float* __restrict__ out)
{
    cudaGridDependencySynchronize();
    const int i = blockIdx.x * 256 + threadIdx.x;      // 65536 float4
    const float4* p = (const float4*)part;
    float4 bv = ((const float4*)bias)[i & 63];
    float4 rv = ((const float4*)res)[i];
    float sx = bv.x + rv.x, sy = bv.y + rv.y, sz = bv.z + rv.z, sw = bv.w + rv.w;
    #pragma unroll
    for (int z = 0; z < KSPLIT; z++) {
        float4 s = p[i + z * 65536];
        sx += s.x; sy += s.y; sz += s.z; sw += s.w;
    }
    float4 o; o.x = sx; o.y = sy; o.z = sz; o.w = sw;
    ((float4*)out)[i] = o;
}

// ---------------------------------------------------------------------------
// L1-distance attention + residual. 128 blocks x 512 threads (16 warps).
// Phase A (per chunk of 128 keys): warp w computes p = exp(1/(eps+dist)) for
//   16 keys (ss=w>>1) x 32 queries (qg=w&1, lane=query), stores to transposed
//   P[key][query] smem chunk (conflict-free: stride 72 = 8 mod 32).
// Phase B: all 16 warps run O[64x32] += P[64x128] @ V[128x32] on tensor cores,
//   one m16n8 tile per warp (mi=w>>2, nj=w&3), accumulating across chunks.
// No cross-warp o-merge needed; only l (softmax denom) is merged.
// smem: K[512][32] 64KB + V[512][40] 80KB + P[128][72] 36KB + lbuf = ~182KB.
// ---------------------------------------------------------------------------
#define ATTN_SMEM 186624
__global__ void attn_kernel(const float* __restrict__ x, const float* __restrict__ qkv,
                            float* __restrict__ x1)
{
    extern __shared__ float sh[];
    float* Kneg = sh;                    // [512][32]  16384 floats
    float* Vsh  = sh + 16384;            // [512][40]  20480 floats (stride 40 = 8 mod 32)
    float* Psh  = sh + 36864;            // [128][72]   9216 floats (stride 72 = 8 mod 32)
    float* lbuf = sh + 46080;            // [64][8]      512
    float* Linv = sh + 46592;            // [64]

    const int bid = blockIdx.x;          // 128 blocks
    const int bh  = bid >> 3;
    const int qb  = bid & 7;
    const int b   = bh >> 3;
    const int hh  = bh & 7;
    const int tid = threadIdx.x;
    const int w   = tid >> 5;
    const int lane = tid & 31;
    const int t0  = qb * 64;

    const int qg = w & 1;                // query group for phase A
    const int ss = w >> 1;               // key sub-range for phase A
    const int q  = qg * 32 + lane;       // this thread's query (0..63)
    const int t  = t0 + q;               // global token index within (b,*)

    const int g  = lane >> 2;            // MMA fragment coords
    const int tg = lane & 3;
    const int mi = w >> 2;               // MMA tile row (0..3)
    const int nj = w & 3;                // MMA tile col (0..3)

    const float* qkv_bh = qkv + (size_t)b * T * 768 + hh * 96;

    cudaGridDependencySynchronize();     // qkv must be complete

    // Stage K (negated) and V (stride 40) for all 512 keys
    for (int i = tid; i < 4096; i += 512) {
        int s = i >> 3, j = i & 7;
        uint4 kv = *(const uint4*)(qkv_bh + (size_t)s * 768 + 32 + j * 4);
        kv.x ^= 0x80000000u; kv.y ^= 0x80000000u;
        kv.z ^= 0x80000000u; kv.w ^= 0x80000000u;
        *(uint4*)(Kneg + s * 32 + j * 4) = kv;
        *(float4*)(Vsh + s * 40 + j * 4) =
            *(const float4*)(qkv_bh + (size_t)s * 768 + 64 + j * 4);
    }

    unsigned long long q2[16];
    {
        const ulonglong2* qsrc = (const ulonglong2*)(qkv_bh + (size_t)t * 768);
        #pragma unroll
        for (int j = 0; j < 8; j++) {
            ulonglong2 v = qsrc[j];
            q2[2 * j] = v.x; q2[2 * j + 1] = v.y;
        }
    }
    __syncthreads();

    const float scale = 0.1767766952966369f;   // 1/sqrt(32)
    const unsigned long long ABSM = 0x7FFFFFFF7FFFFFFFULL;
    float l = 0.f;
    float acc[4] = {};

    #pragma unroll 1
    for (int ch = 0; ch < 4; ch++) {
        // ---- Phase A: p for 16 keys x 32 queries per warp ----
        #pragma unroll 2
        for (int i2 = 0; i2 < 16; i2++) {
            const int kc = ss * 16 + i2;         // key within chunk (0..127)
            const int sg = ch * 128 + kc;        // global key
            const ulonglong2* krow = (const ulonglong2*)(Kneg + sg * 32); // broadcast
            unsigned long long accA = 0ULL, accB = 0ULL;
            #pragma unroll
            for (int j = 0; j < 8; j++) {
                ulonglong2 kk = krow[j];
                unsigned long long d0 = addx2(q2[2 * j],     kk.x) & ABSM;
                unsigned long long d1 = addx2(q2[2 * j + 1], kk.y) & ABSM;
                accA = addx2(accA, d0);
                accB = addx2(accB, d1);
            }
            float a0, a1, b0, b1;
            unpack2(accA, a0, a1);
            unpack2(accB, b0, b1);
            float dist = (a0 + a1) + (b0 + b1);
            float wgt = (sg == t) ? 0.f : __fdividef(1.f, 0.001f + dist * scale);
            float p = __expf(wgt);               // direct exp: wgt in [0, ~1.5]
            l += p;
            Psh[kc * 72 + q] = p;                // transposed store, conflict-free
        }
        __syncthreads();

        // ---- Phase B: O += P @ V_chunk (tensor cores) ----
        const float* Vch = Vsh + ch * 128 * 40;
        #pragma unroll
        for (int ks = 0; ks < 16; ks++) {
            const int kk = ks * 8;
            unsigned a0 = __float_as_uint(Psh[(kk + tg    ) * 72 + mi * 16 + g    ]);
            unsigned a1 = __float_as_uint(Psh[(kk + tg    ) * 72 + mi * 16 + g + 8]);
            unsigned a2 = __float_as_uint(Psh[(kk + tg + 4) * 72 + mi * 16 + g    ]);
            unsigned a3 = __float_as_uint(Psh[(kk + tg + 4) * 72 + mi * 16 + g + 8]);
            unsigned b0 = __float_as_uint(Vch[(kk + tg    ) * 40 + nj * 8 + g]);
            unsigned b1 = __float_as_uint(Vch[(kk + tg + 4) * 40 + nj * 8 + g]);
            asm volatile(
                "mma.sync.aligned.m16n8k8.row.col.f32.tf32.tf32.f32 "
                "{%0,%1,%2,%3}, {%4,%5,%6,%7}, {%8,%9}, {%0,%1,%2,%3};"
                : "+f"(acc[0]), "+f"(acc[1]), "+f"(acc[2]), "+f"(acc[3])
                : "r"(a0), "r"(a1), "r"(a2), "r"(a3), "r"(b0), "r"(b1));
        }
        __syncthreads();   // before next chunk overwrites Psh
    }

    // l merge
    lbuf[q * 8 + ss] = l;
    __syncthreads();
    if (tid < 64) {
        float L = 0.f;
        #pragma unroll
        for (int i = 0; i < 8; i++) L += lbuf[tid * 8 + i];
        Linv[tid] = __fdividef(1.f, L);
    }
    __syncthreads();

    // Epilogue: each warp owns output tile rows [16mi+g, +8], cols [8nj+2tg, +1]
    {
        const int c0 = nj * 8 + tg * 2;
        #pragma unroll
        for (int rg = 0; rg < 2; rg++) {
            const int r = mi * 16 + g + rg * 8;        // query row 0..63
            float inv = Linv[r];
            size_t idx = ((size_t)b * T + (t0 + r)) * DM + hh * HC + c0;
            float2 xv = *(const float2*)&x[idx];
            float2 o;
            o.x = xv.x + acc[rg * 2 + 0] * inv;
            o.y = xv.y + acc[rg * 2 + 1] * inv;
            *(float2*)&x1[idx] = o;
        }
    }
    cudaTriggerProgrammaticLaunchCompletion();   // after stores
}

// ---------------------------------------------------------------------------
template<typename K, typename... Args>
static void launch_pdl(K kernel, dim3 grid, dim3 block, unsigned smem, Args... args)
{
    cudaLaunchAttribute attr[1];
    attr[0].id = cudaLaunchAttributeProgrammaticStreamSerialization;
    attr[0].val.programmaticStreamSerializationAllowed = 1;
    cudaLaunchConfig_t cfg{};
    cfg.gridDim = grid;
    cfg.blockDim = block;
    cfg.dynamicSmemBytes = smem;
    cfg.stream = 0;
    cfg.attrs = attr;
    cfg.numAttrs = 1;
    cudaLaunchKernelEx(&cfg, kernel, args...);
}

extern "C" void kernel_launch(void* const* d_in, const int* in_sizes, int n_in,
                              void* d_out, int out_size)
{
    const float* x      = (const float*)d_in[0];
    const float* W_qkv  = (const float*)d_in[1];
    const float* b_qkv  = (const float*)d_in[2];
    const float* W_fc   = (const float*)d_in[3];
    const float* b_fc   = (const float*)d_in[4];
    const float* W_proj = (const float*)d_in[5];
    const float* b_proj = (const float*)d_in[6];
    float* out = (float*)d_out;

    float *p_qkv, *p_x1, *p_h, *p_part;
    cudaGetSymbolAddress((void**)&p_qkv,  g_qkv);
    cudaGetSymbolAddress((void**)&p_x1,   g_x1);
    cudaGetSymbolAddress((void**)&p_h,    g_h);
    cudaGetSymbolAddress((void**)&p_part, g_part);

    static bool cfgd = false;
    if (!cfgd) {
        cudaFuncSetAttribute(attn_kernel, cudaFuncAttributeMaxDynamicSharedMemorySize, ATTN_SMEM);
        cfgd = true;
    }

    // 1) qkv = x @ W_qkv + b_qkv            (1024 x 768, K=256) grid 192
    launch_pdl(gemm_tc<0, false, false, false>, dim3(12, 16), dim3(256), 0,
               x, W_qkv, b_qkv, (const float*)nullptr, p_qkv, NTOK, 3 * DM, DM, DM);

    // 2) x1 = x + attention(qkv)
    launch_pdl(attn_kernel, dim3(128), dim3(512), ATTN_SMEM, x, p_qkv, p_x1);

    // 3) h = quick_gelu(x1 @ W_fc + b_fc)   (1024 x 1024, K=256) grid 256
    launch_pdl(gemm_tc<1, false, false, true>, dim3(16, 16), dim3(256), 0,
               p_x1, W_fc, b_fc, (const float*)nullptr, p_h, NTOK, 4 * DM, DM, DM);

    // 4) proj split-K x8 in ONE launch      (1024 x 256, Ksplit=128) grid 512
    launch_pdl(gemm_tc<0, false, true, true>, dim3(4, 16, KSPLIT), dim3(256), 0,
               p_h, W_proj, (const float*)nullptr, (const float*)nullptr,
               p_part, NTOK, DM, 1024 / KSPLIT, 4 * DM);

    // 5) out = sum(partials) + b_proj + x1
    launch_pdl(reduce_proj, dim3(256), dim3(256), 0, p_part, b_proj, p_x1, out);
}

// round 14
// speedup vs baseline: 1.0357x; 1.0047x over previous
#include <cuda_runtime.h>
#include <cuda_bf16.h>
#include <math.h>

// Shapes (fixed): B=2, T=512, D=256, H=8, c=32
#define NTOK 1024
#define DM   256
#define NH   8
#define HC   32
#define T    512
#define KSPLIT 8

__device__ float g_qkv [NTOK * 3 * DM];          // 1024 x 768
__device__ float g_x1  [NTOK * DM];              // 1024 x 256
__device__ float g_h   [NTOK * 4 * DM];          // 1024 x 1024

__device__ __forceinline__ void cp16(void* smem_dst, const void* gsrc) {
    unsigned s = (unsigned)__cvta_generic_to_shared(smem_dst);
    asm volatile("cp.async.cg.shared.global [%0], [%1], 16;\n" :: "r"(s), "l"(gsrc));
}

// packed f32x2 helpers (sm_100+)
__device__ __forceinline__ unsigned long long addx2(unsigned long long a, unsigned long long b) {
    unsigned long long d;
    asm("add.rn.f32x2 %0, %1, %2;" : "=l"(d) : "l"(a), "l"(b));
    return d;
}
__device__ __forceinline__ void unpack2(unsigned long long v, float& lo, float& hi) {
    asm("mov.b64 {%0, %1}, %2;" : "=f"(lo), "=f"(hi) : "l"(v));
}

// ---------------------------------------------------------------------------
// TF32 tensor-core GEMM, 3-stage cp.async pipeline, split-K via blockIdx.z.
// BM=64, BN=64, BK=32, 256 threads, warp tile 32x16.
// RED=true: epilogue does atomicAdd (REDG) of bare partial sums into C,
// which must be pre-seeded with bias + residual by an earlier kernel.
// ---------------------------------------------------------------------------
template<int ACT, bool RES, bool RED, bool DEP>
__global__ void gemm_tc(const float* __restrict__ A, const float* __restrict__ B,
                        const float* __restrict__ bias, const float* __restrict__ res,
                        float* __restrict__ C, int M, int N, int Klen, int lda)
{
    __shared__ float As[3][64 * 36];
    __shared__ float Bs[3][32 * 68];

    const int tid  = threadIdx.x;
    const int w    = tid >> 5;
    const int lane = tid & 31;
    const int g    = lane >> 2;
    const int tg   = lane & 3;
    const int warpM = w >> 2;
    const int warpN = w & 3;

    const int row0 = blockIdx.y * 64;
    const int col0 = blockIdx.x * 64;

    const int kz = blockIdx.z * Klen;
    A += kz;
    B += (size_t)kz * N;

    float acc[2][2][4] = {};

    auto loadA = [&](int k0, int buf) {
        #pragma unroll
        for (int c = tid; c < 512; c += 256) {
            int rA = c >> 3, cA = (c & 7) * 4;
            cp16(&As[buf][rA * 36 + cA], A + (size_t)(row0 + rA) * lda + k0 + cA);
        }
    };
    auto loadB = [&](int k0, int buf) {
        #pragma unroll
        for (int c = tid; c < 512; c += 256) {
            int rB = c >> 4, cB = (c & 15) * 4;
            cp16(&Bs[buf][rB * 68 + cB], B + (size_t)(k0 + rB) * N + col0 + cB);
        }
    };

    const int nt = Klen >> 5;

    loadB(0, 0);
    if (nt > 1) loadB(32, 1);
    if (DEP) cudaGridDependencySynchronize();
    loadA(0, 0);
    asm volatile("cp.async.commit_group;\n");
    if (nt > 1) {
        loadA(32, 1);
        asm volatile("cp.async.commit_group;\n");
    }

    for (int i = 0; i < nt; i++) {
        if (i + 2 < nt) {
            loadB((i + 2) << 5, (i + 2) % 3);
            loadA((i + 2) << 5, (i + 2) % 3);
            asm volatile("cp.async.commit_group;\n");
            asm volatile("cp.async.wait_group 2;\n");
        } else if (i + 1 < nt) {
            asm volatile("cp.async.wait_group 1;\n");
        } else {
            asm volatile("cp.async.wait_group 0;\n");
        }
        __syncthreads();

        const float* Ab = As[i % 3];
        const float* Bb = Bs[i % 3];

        #pragma unroll
        for (int ks = 0; ks < 4; ks++) {
            const int kk = ks * 8;
            unsigned a[2][4], b[2][2];
            #pragma unroll
            for (int ii = 0; ii < 2; ii++) {
                const int rb = warpM * 32 + ii * 16;
                a[ii][0] = __float_as_uint(Ab[(rb + g    ) * 36 + kk + tg    ]);
                a[ii][1] = __float_as_uint(Ab[(rb + g + 8) * 36 + kk + tg    ]);
                a[ii][2] = __float_as_uint(Ab[(rb + g    ) * 36 + kk + tg + 4]);
                a[ii][3] = __float_as_uint(Ab[(rb + g + 8) * 36 + kk + tg + 4]);
            }
            #pragma unroll
            for (int j = 0; j < 2; j++) {
                const int cb = warpN * 16 + j * 8;
                b[j][0] = __float_as_uint(Bb[(kk + tg    ) * 68 + cb + g]);
                b[j][1] = __float_as_uint(Bb[(kk + tg + 4) * 68 + cb + g]);
            }
            #pragma unroll
            for (int ii = 0; ii < 2; ii++)
                #pragma unroll
                for (int j = 0; j < 2; j++) {
                    asm volatile(
                        "mma.sync.aligned.m16n8k8.row.col.f32.tf32.tf32.f32 "
                        "{%0,%1,%2,%3}, {%4,%5,%6,%7}, {%8,%9}, {%0,%1,%2,%3};"
                        : "+f"(acc[ii][j][0]), "+f"(acc[ii][j][1]),
                          "+f"(acc[ii][j][2]), "+f"(acc[ii][j][3])
                        : "r"(a[ii][0]), "r"(a[ii][1]), "r"(a[ii][2]), "r"(a[ii][3]),
                          "r"(b[j][0]), "r"(b[j][1]));
                }
        }
        __syncthreads();
    }

    #pragma unroll
    for (int ii = 0; ii < 2; ii++) {
        const int rb = row0 + warpM * 32 + ii * 16;
        #pragma unroll
        for (int j = 0; j < 2; j++) {
            const int cb = col0 + warpN * 16 + j * 8;
            #pragma unroll
            for (int rg = 0; rg < 2; rg++) {
                const int r = rb + g + rg * 8;
                const int c = cb + tg * 2;
                float v0 = acc[ii][j][rg * 2 + 0];
                float v1 = acc[ii][j][rg * 2 + 1];
                if (RED) {
                    atomicAdd(&C[(size_t)r * N + c],     v0);   // REDG (no return)
                    atomicAdd(&C[(size_t)r * N + c + 1], v1);
                } else {
                    v0 += bias[c];
                    v1 += bias[c + 1];
                    if (ACT == 1) {
                        v0 = v0 * __fdividef(1.f, 1.f + __expf(-1.702f * v0));
                        v1 = v1 * __fdividef(1.f, 1.f + __expf(-1.702f * v1));
                    }
                    if (RES) {
                        float2 rv = *(const float2*)&res[(size_t)r * N + c];
                        v0 += rv.x; v1 += rv.y;
                    }
                    float2 o; o.x = v0; o.y = v1;
                    *(float2*)&C[(size_t)r * N + c] = o;
                }
            }
        }
    }
    cudaTriggerProgrammaticLaunchCompletion();   // after stores
}

// ---------------------------------------------------------------------------
// L1-distance attention + residual. 128 blocks x 512 threads (16 warps).
// Phase A: per chunk of 128 keys, warp w computes p for 16 keys x 32 queries,
// stores transposed P[key][query] (stride 72, conflict-free).
// Phase B: O[64x32] += P @ V_chunk on tensor cores, one m16n8 tile per warp.
// Epilogue writes x1 = x + attn AND seeds out = x1 + b_proj (proj REDs later).
// ---------------------------------------------------------------------------
#define ATTN_SMEM 186624
__global__ void attn_kernel(const float* __restrict__ x, const float* __restrict__ qkv,
                            const float* __restrict__ b_proj,
                            float* __restrict__ x1, float* __restrict__ outseed)
{
    extern __shared__ float sh[];
    float* Kneg = sh;                    // [512][32]  16384 floats
    float* Vsh  = sh + 16384;            // [512][40]  20480 floats
    float* Psh  = sh + 36864;            // [128][72]   9216 floats
    float* lbuf = sh + 46080;            // [64][8]
    float* Linv = sh + 46592;            // [64]

    const int bid = blockIdx.x;
    const int bh  = bid >> 3;
    const int qb  = bid & 7;
    const int b   = bh >> 3;
    const int hh  = bh & 7;
    const int tid = threadIdx.x;
    const int w   = tid >> 5;
    const int lane = tid & 31;
    const int t0  = qb * 64;

    const int qg = w & 1;
    const int ss = w >> 1;
    const int q  = qg * 32 + lane;
    const int t  = t0 + q;

    const int g  = lane >> 2;
    const int tg = lane & 3;
    const int mi = w >> 2;
    const int nj = w & 3;

    const float* qkv_bh = qkv + (size_t)b * T * 768 + hh * 96;

    cudaGridDependencySynchronize();     // qkv must be complete

    for (int i = tid; i < 4096; i += 512) {
        int s = i >> 3, j = i & 7;
        uint4 kv = *(const uint4*)(qkv_bh + (size_t)s * 768 + 32 + j * 4);
        kv.x ^= 0x80000000u; kv.y ^= 0x80000000u;
        kv.z ^= 0x80000000u; kv.w ^= 0x80000000u;
        *(uint4*)(Kneg + s * 32 + j * 4) = kv;
        *(float4*)(Vsh + s * 40 + j * 4) =
            *(const float4*)(qkv_bh + (size_t)s * 768 + 64 + j * 4);
    }

    unsigned long long q2[16];
    {
        const ulonglong2* qsrc = (const ulonglong2*)(qkv_bh + (size_t)t * 768);
        #pragma unroll
        for (int j = 0; j < 8; j++) {
            ulonglong2 v = qsrc[j];
            q2[2 * j] = v.x; q2[2 * j + 1] = v.y;
        }
    }
    __syncthreads();

    const float scale = 0.1767766952966369f;
    const unsigned long long ABSM = 0x7FFFFFFF7FFFFFFFULL;
    float l = 0.f;
    float acc[4] = {};

    #pragma unroll 1
    for (int ch = 0; ch < 4; ch++) {
        #pragma unroll 2
        for (int i2 = 0; i2 < 16; i2++) {
            const int kc = ss * 16 + i2;
            const int sg = ch * 128 + kc;
            const ulonglong2* krow = (const ulonglong2*)(Kneg + sg * 32);
            unsigned long long accA = 0ULL, accB = 0ULL;
            #pragma unroll
            for (int j = 0; j < 8; j++) {
                ulonglong2 kk = krow[j];
                unsigned long long d0 = addx2(q2[2 * j],     kk.x) & ABSM;
                unsigned long long d1 = addx2(q2[2 * j + 1], kk.y) & ABSM;
                accA = addx2(accA, d0);
                accB = addx2(accB, d1);
            }
            float a0, a1, b0, b1;
            unpack2(accA, a0, a1);
            unpack2(accB, b0, b1);
            float dist = (a0 + a1) + (b0 + b1);
            float wgt = (sg == t) ? 0.f : __fdividef(1.f, 0.001f + dist * scale);
            float p = __expf(wgt);
            l += p;
            Psh[kc * 72 + q] = p;
        }
        __syncthreads();

        const float* Vch = Vsh + ch * 128 * 40;
        #pragma unroll
        for (int ks = 0; ks < 16; ks++) {
            const int kk = ks * 8;
            unsigned a0 = __float_as_uint(Psh[(kk + tg    ) * 72 + mi * 16 + g    ]);
            unsigned a1 = __float_as_uint(Psh[(kk + tg    ) * 72 + mi * 16 + g + 8]);
            unsigned a2 = __float_as_uint(Psh[(kk + tg + 4) * 72 + mi * 16 + g    ]);
            unsigned a3 = __float_as_uint(Psh[(kk + tg + 4) * 72 + mi * 16 + g + 8]);
            unsigned b0 = __float_as_uint(Vch[(kk + tg    ) * 40 + nj * 8 + g]);
            unsigned b1 = __float_as_uint(Vch[(kk + tg + 4) * 40 + nj * 8 + g]);
            asm volatile(
                "mma.sync.aligned.m16n8k8.row.col.f32.tf32.tf32.f32 "
                "{%0,%1,%2,%3}, {%4,%5,%6,%7}, {%8,%9}, {%0,%1,%2,%3};"
                : "+f"(acc[0]), "+f"(acc[1]), "+f"(acc[2]), "+f"(acc[3])
                : "r"(a0), "r"(a1), "r"(a2), "r"(a3), "r"(b0), "r"(b1));
        }
        __syncthreads();
    }

    lbuf[q * 8 + ss] = l;
    __syncthreads();
    if (tid < 64) {
        float L = 0.f;
        #pragma unroll
        for (int i = 0; i < 8; i++) L += lbuf[tid * 8 + i];
        Linv[tid] = __fdividef(1.f, L);
    }
    __syncthreads();

    // Epilogue: x1 = x + attn ; outseed = x1 + b_proj (proj REDs on top)
    {
        const int c0 = nj * 8 + tg * 2;
        float2 bp = *(const float2*)&b_proj[hh * HC + c0];
        #pragma unroll
        for (int rg = 0; rg < 2; rg++) {
            const int r = mi * 16 + g + rg * 8;
            float inv = Linv[r];
            size_t idx = ((size_t)b * T + (t0 + r)) * DM + hh * HC + c0;
            float2 xv = *(const float2*)&x[idx];
            float2 o;
            o.x = xv.x + acc[rg * 2 + 0] * inv;
            o.y = xv.y + acc[rg * 2 + 1] * inv;
            *(float2*)&x1[idx] = o;
            float2 osd; osd.x = o.x + bp.x; osd.y = o.y + bp.y;
            *(float2*)&outseed[idx] = osd;
        }
    }
    cudaTriggerProgrammaticLaunchCompletion();   // after stores
}

// ---------------------------------------------------------------------------
template<typename K, typename... Args>
static void launch_pdl(K kernel, dim3 grid, dim3 block, unsigned smem, Args... args)
{
    cudaLaunchAttribute attr[1];
    attr[0].id = cudaLaunchAttributeProgrammaticStreamSerialization;
    attr[0].val.programmaticStreamSerializationAllowed = 1;
    cudaLaunchConfig_t cfg{};
    cfg.gridDim = grid;
    cfg.blockDim = block;
    cfg.dynamicSmemBytes = smem;
    cfg.stream = 0;
    cfg.attrs = attr;
    cfg.numAttrs = 1;
    cudaLaunchKernelEx(&cfg, kernel, args...);
}

extern "C" void kernel_launch(void* const* d_in, const int* in_sizes, int n_in,
                              void* d_out, int out_size)
{
    const float* x      = (const float*)d_in[0];
    const float* W_qkv  = (const float*)d_in[1];
    const float* b_qkv  = (const float*)d_in[2];
    const float* W_fc   = (const float*)d_in[3];
    const float* b_fc   = (const float*)d_in[4];
    const float* W_proj = (const float*)d_in[5];
    const float* b_proj = (const float*)d_in[6];
    float* out = (float*)d_out;

    float *p_qkv, *p_x1, *p_h;
    cudaGetSymbolAddress((void**)&p_qkv,  g_qkv);
    cudaGetSymbolAddress((void**)&p_x1,   g_x1);
    cudaGetSymbolAddress((void**)&p_h,    g_h);

    static bool cfgd = false;
    if (!cfgd) {
        cudaFuncSetAttribute(attn_kernel, cudaFuncAttributeMaxDynamicSharedMemorySize, ATTN_SMEM);
        cfgd = true;
    }

    // 1) qkv = x @ W_qkv + b_qkv            (1024 x 768, K=256) grid 192
    launch_pdl(gemm_tc<0, false, false, false>, dim3(12, 16), dim3(256), 0,
               x, W_qkv, b_qkv, (const float*)nullptr, p_qkv, NTOK, 3 * DM, DM, DM);

    // 2) x1 = x + attention(qkv); out seeded with x1 + b_proj
    launch_pdl(attn_kernel, dim3(128), dim3(512), ATTN_SMEM,
               x, p_qkv, b_proj, p_x1, out);

    // 3) h = quick_gelu(x1 @ W_fc + b_fc)   (1024 x 1024, K=256) grid 256
    launch_pdl(gemm_tc<1, false, false, true>, dim3(16, 16), dim3(256), 0,
               p_x1, W_fc, b_fc, (const float*)nullptr, p_h, NTOK, 4 * DM, DM, DM);

    // 4) out += h @ W_proj via REDG, split-K x8 (1024 x 256, Ksplit=128) grid 512
    launch_pdl(gemm_tc<0, false, true, true>, dim3(4, 16, KSPLIT), dim3(256), 0,
               p_h, W_proj, (const float*)nullptr, (const float*)nullptr,
               out, NTOK, DM, 1024 / KSPLIT, 4 * DM);
}

// round 15
// speedup vs baseline: 1.0643x; 1.0276x over previous
#include <cuda_runtime.h>
#include <cuda_bf16.h>
#include <math.h>

// Shapes (fixed): B=2, T=512, D=256, H=8, c=32
#define NTOK 1024
#define DM   256
#define NH   8
#define HC   32
#define T    512
#define KSPLIT 8

__device__ float g_qkv [NTOK * 3 * DM];          // 1024 x 768
__device__ float g_x1  [NTOK * DM];              // 1024 x 256
__device__ float g_h   [NTOK * 4 * DM];          // 1024 x 1024

__device__ __forceinline__ void cp16(void* smem_dst, const void* gsrc) {
    unsigned s = (unsigned)__cvta_generic_to_shared(smem_dst);
    asm volatile("cp.async.cg.shared.global [%0], [%1], 16;\n" :: "r"(s), "l"(gsrc));
}

__device__ __forceinline__ void red2(float* gaddr, float v0, float v1) {
    asm volatile("red.global.add.v2.f32 [%0], {%1, %2};\n"
                 :: "l"(gaddr), "f"(v0), "f"(v1) : "memory");
}

// packed f32x2 helpers (sm_100+)
__device__ __forceinline__ unsigned long long addx2(unsigned long long a, unsigned long long b) {
    unsigned long long d;
    asm("add.rn.f32x2 %0, %1, %2;" : "=l"(d) : "l"(a), "l"(b));
    return d;
}
__device__ __forceinline__ void unpack2(unsigned long long v, float& lo, float& hi) {
    asm("mov.b64 {%0, %1}, %2;" : "=f"(lo), "=f"(hi) : "l"(v));
}

// ---------------------------------------------------------------------------
// TF32 tensor-core GEMM, 4-stage cp.async pipeline, split-K via blockIdx.z.
// BM=64, BN=64, BK=32, 256 threads, warp tile 32x16.
// RED=true: epilogue red.global.v2 of bare partials into pre-seeded C.
// Requires nt = Klen/32 >= 3 (true for all launches here: nt 4 or 8).
// ---------------------------------------------------------------------------
template<int ACT, bool RES, bool RED, bool DEP>
__global__ void gemm_tc(const float* __restrict__ A, const float* __restrict__ B,
                        const float* __restrict__ bias, const float* __restrict__ res,
                        float* __restrict__ C, int M, int N, int Klen, int lda)
{
    __shared__ float As[4][64 * 36];
    __shared__ float Bs[4][32 * 68];

    const int tid  = threadIdx.x;
    const int w    = tid >> 5;
    const int lane = tid & 31;
    const int g    = lane >> 2;
    const int tg   = lane & 3;
    const int warpM = w >> 2;
    const int warpN = w & 3;

    const int row0 = blockIdx.y * 64;
    const int col0 = blockIdx.x * 64;

    const int kz = blockIdx.z * Klen;
    A += kz;
    B += (size_t)kz * N;

    float acc[2][2][4] = {};

    auto loadA = [&](int k0, int buf) {
        #pragma unroll
        for (int c = tid; c < 512; c += 256) {
            int rA = c >> 3, cA = (c & 7) * 4;
            cp16(&As[buf][rA * 36 + cA], A + (size_t)(row0 + rA) * lda + k0 + cA);
        }
    };
    auto loadB = [&](int k0, int buf) {
        #pragma unroll
        for (int c = tid; c < 512; c += 256) {
            int rB = c >> 4, cB = (c & 15) * 4;
            cp16(&Bs[buf][rB * 68 + cB], B + (size_t)(k0 + rB) * N + col0 + cB);
        }
    };

    const int nt = Klen >> 5;   // >= 3 assumed

    // Prologue: independent weight tiles for stages 0..2 first, then sync,
    // then the dependent activation tiles. G0={B0,B1,B2,A0}, G1={A1}, G2={A2}.
    loadB(0, 0);
    loadB(32, 1);
    loadB(64, 2);
    if (DEP) cudaGridDependencySynchronize();
    loadA(0, 0);
    asm volatile("cp.async.commit_group;\n");
    loadA(32, 1);
    asm volatile("cp.async.commit_group;\n");
    loadA(64, 2);
    asm volatile("cp.async.commit_group;\n");

    for (int i = 0; i < nt; i++) {
        if (i + 3 < nt) {
            loadB((i + 3) << 5, (i + 3) & 3);
            loadA((i + 3) << 5, (i + 3) & 3);
            asm volatile("cp.async.commit_group;\n");
            asm volatile("cp.async.wait_group 3;\n");
        } else if (i + 2 < nt) {
            asm volatile("cp.async.wait_group 2;\n");
        } else if (i + 1 < nt) {
            asm volatile("cp.async.wait_group 1;\n");
        } else {
            asm volatile("cp.async.wait_group 0;\n");
        }
        __syncthreads();

        const float* Ab = As[i & 3];
        const float* Bb = Bs[i & 3];

        #pragma unroll
        for (int ks = 0; ks < 4; ks++) {
            const int kk = ks * 8;
            unsigned a[2][4], b[2][2];
            #pragma unroll
            for (int ii = 0; ii < 2; ii++) {
                const int rb = warpM * 32 + ii * 16;
                a[ii][0] = __float_as_uint(Ab[(rb + g    ) * 36 + kk + tg    ]);
                a[ii][1] = __float_as_uint(Ab[(rb + g + 8) * 36 + kk + tg    ]);
                a[ii][2] = __float_as_uint(Ab[(rb + g    ) * 36 + kk + tg + 4]);
                a[ii][3] = __float_as_uint(Ab[(rb + g + 8) * 36 + kk + tg + 4]);
            }
            #pragma unroll
            for (int j = 0; j < 2; j++) {
                const int cb = warpN * 16 + j * 8;
                b[j][0] = __float_as_uint(Bb[(kk + tg    ) * 68 + cb + g]);
                b[j][1] = __float_as_uint(Bb[(kk + tg + 4) * 68 + cb + g]);
            }
            #pragma unroll
            for (int ii = 0; ii < 2; ii++)
                #pragma unroll
                for (int j = 0; j < 2; j++) {
                    asm volatile(
                        "mma.sync.aligned.m16n8k8.row.col.f32.tf32.tf32.f32 "
                        "{%0,%1,%2,%3}, {%4,%5,%6,%7}, {%8,%9}, {%0,%1,%2,%3};"
                        : "+f"(acc[ii][j][0]), "+f"(acc[ii][j][1]),
                          "+f"(acc[ii][j][2]), "+f"(acc[ii][j][3])
                        : "r"(a[ii][0]), "r"(a[ii][1]), "r"(a[ii][2]), "r"(a[ii][3]),
                          "r"(b[j][0]), "r"(b[j][1]));
                }
        }
        __syncthreads();
    }

    #pragma unroll
    for (int ii = 0; ii < 2; ii++) {
        const int rb = row0 + warpM * 32 + ii * 16;
        #pragma unroll
        for (int j = 0; j < 2; j++) {
            const int cb = col0 + warpN * 16 + j * 8;
            #pragma unroll
            for (int rg = 0; rg < 2; rg++) {
                const int r = rb + g + rg * 8;
                const int c = cb + tg * 2;
                float v0 = acc[ii][j][rg * 2 + 0];
                float v1 = acc[ii][j][rg * 2 + 1];
                if (RED) {
                    red2(&C[(size_t)r * N + c], v0, v1);   // vector REDG
                } else {
                    v0 += bias[c];
                    v1 += bias[c + 1];
                    if (ACT == 1) {
                        v0 = v0 * __fdividef(1.f, 1.f + __expf(-1.702f * v0));
                        v1 = v1 * __fdividef(1.f, 1.f + __expf(-1.702f * v1));
                    }
                    if (RES) {
                        float2 rv = *(const float2*)&res[(size_t)r * N + c];
                        v0 += rv.x; v1 += rv.y;
                    }
                    float2 o; o.x = v0; o.y = v1;
                    *(float2*)&C[(size_t)r * N + c] = o;
                }
            }
        }
    }
    cudaTriggerProgrammaticLaunchCompletion();   // after stores
}

// ---------------------------------------------------------------------------
// L1-distance attention + residual. 128 blocks x 512 threads (16 warps).
// Phase A: per chunk of 128 keys, warp w computes p for 16 keys x 32 queries,
// stores transposed P[key][query] (stride 72, conflict-free).
// Phase B: O[64x32] += P @ V_chunk on tensor cores, one m16n8 tile per warp.
// Epilogue writes x1 = x + attn AND seeds out = x1 + b_proj (proj REDs later).
// ---------------------------------------------------------------------------
#define ATTN_SMEM 186624
__global__ void attn_kernel(const float* __restrict__ x, const float* __restrict__ qkv,
                            const float* __restrict__ b_proj,
                            float* __restrict__ x1, float* __restrict__ outseed)
{
    extern __shared__ float sh[];
    float* Kneg = sh;                    // [512][32]  16384 floats
    float* Vsh  = sh + 16384;            // [512][40]  20480 floats
    float* Psh  = sh + 36864;            // [128][72]   9216 floats
    float* lbuf = sh + 46080;            // [64][8]
    float* Linv = sh + 46592;            // [64]

    const int bid = blockIdx.x;
    const int bh  = bid >> 3;
    const int qb  = bid & 7;
    const int b   = bh >> 3;
    const int hh  = bh & 7;
    const int tid = threadIdx.x;
    const int w   = tid >> 5;
    const int lane = tid & 31;
    const int t0  = qb * 64;

    const int qg = w & 1;
    const int ss = w >> 1;
    const int q  = qg * 32 + lane;
    const int t  = t0 + q;

    const int g  = lane >> 2;
    const int tg = lane & 3;
    const int mi = w >> 2;
    const int nj = w & 3;

    const float* qkv_bh = qkv + (size_t)b * T * 768 + hh * 96;

    cudaGridDependencySynchronize();     // qkv must be complete

    for (int i = tid; i < 4096; i += 512) {
        int s = i >> 3, j = i & 7;
        uint4 kv = *(const uint4*)(qkv_bh + (size_t)s * 768 + 32 + j * 4);
        kv.x ^= 0x80000000u; kv.y ^= 0x80000000u;
        kv.z ^= 0x80000000u; kv.w ^= 0x80000000u;
        *(uint4*)(Kneg + s * 32 + j * 4) = kv;
        *(float4*)(Vsh + s * 40 + j * 4) =
            *(const float4*)(qkv_bh + (size_t)s * 768 + 64 + j * 4);
    }

    unsigned long long q2[16];
    {
        const ulonglong2* qsrc = (const ulonglong2*)(qkv_bh + (size_t)t * 768);
        #pragma unroll
        for (int j = 0; j < 8; j++) {
            ulonglong2 v = qsrc[j];
            q2[2 * j] = v.x; q2[2 * j + 1] = v.y;
        }
    }
    __syncthreads();

    const float scale = 0.1767766952966369f;
    const unsigned long long ABSM = 0x7FFFFFFF7FFFFFFFULL;
    float l = 0.f;
    float acc[4] = {};

    #pragma unroll 1
    for (int ch = 0; ch < 4; ch++) {
        #pragma unroll 2
        for (int i2 = 0; i2 < 16; i2++) {
            const int kc = ss * 16 + i2;
            const int sg = ch * 128 + kc;
            const ulonglong2* krow = (const ulonglong2*)(Kneg + sg * 32);
            unsigned long long accA = 0ULL, accB = 0ULL;
            #pragma unroll
            for (int j = 0; j < 8; j++) {
                ulonglong2 kk = krow[j];
                unsigned long long d0 = addx2(q2[2 * j],     kk.x) & ABSM;
                unsigned long long d1 = addx2(q2[2 * j + 1], kk.y) & ABSM;
                accA = addx2(accA, d0);
                accB = addx2(accB, d1);
            }
            float a0, a1, b0, b1;
            unpack2(accA, a0, a1);
            unpack2(accB, b0, b1);
            float dist = (a0 + a1) + (b0 + b1);
            float wgt = (sg == t) ? 0.f : __fdividef(1.f, 0.001f + dist * scale);
            float p = __expf(wgt);
            l += p;
            Psh[kc * 72 + q] = p;
        }
        __syncthreads();

        const float* Vch = Vsh + ch * 128 * 40;
        #pragma unroll
        for (int ks = 0; ks < 16; ks++) {
            const int kk = ks * 8;
            unsigned a0 = __float_as_uint(Psh[(kk + tg    ) * 72 + mi * 16 + g    ]);
            unsigned a1 = __float_as_uint(Psh[(kk + tg    ) * 72 + mi * 16 + g + 8]);
            unsigned a2 = __float_as_uint(Psh[(kk + tg + 4) * 72 + mi * 16 + g    ]);
            unsigned a3 = __float_as_uint(Psh[(kk + tg + 4) * 72 + mi * 16 + g + 8]);
            unsigned b0 = __float_as_uint(Vch[(kk + tg    ) * 40 + nj * 8 + g]);
            unsigned b1 = __float_as_uint(Vch[(kk + tg + 4) * 40 + nj * 8 + g]);
            asm volatile(
                "mma.sync.aligned.m16n8k8.row.col.f32.tf32.tf32.f32 "
                "{%0,%1,%2,%3}, {%4,%5,%6,%7}, {%8,%9}, {%0,%1,%2,%3};"
                : "+f"(acc[0]), "+f"(acc[1]), "+f"(acc[2]), "+f"(acc[3])
                : "r"(a0), "r"(a1), "r"(a2), "r"(a3), "r"(b0), "r"(b1));
        }
        __syncthreads();
    }

    lbuf[q * 8 + ss] = l;
    __syncthreads();
    if (tid < 64) {
        float L = 0.f;
        #pragma unroll
        for (int i = 0; i < 8; i++) L += lbuf[tid * 8 + i];
        Linv[tid] = __fdividef(1.f, L);
    }
    __syncthreads();

    // Epilogue: x1 = x + attn ; outseed = x1 + b_proj (proj REDs on top)
    {
        const int c0 = nj * 8 + tg * 2;
        float2 bp = *(const float2*)&b_proj[hh * HC + c0];
        #pragma unroll
        for (int rg = 0; rg < 2; rg++) {
            const int r = mi * 16 + g + rg * 8;
            float inv = Linv[r];
            size_t idx = ((size_t)b * T + (t0 + r)) * DM + hh * HC + c0;
            float2 xv = *(const float2*)&x[idx];
            float2 o;
            o.x = xv.x + acc[rg * 2 + 0] * inv;
            o.y = xv.y + acc[rg * 2 + 1] * inv;
            *(float2*)&x1[idx] = o;
            float2 osd; osd.x = o.x + bp.x; osd.y = o.y + bp.y;
            *(float2*)&outseed[idx] = osd;
        }
    }
    cudaTriggerProgrammaticLaunchCompletion();   // after stores
}

// ---------------------------------------------------------------------------
template<typename K, typename... Args>
static void launch_pdl(K kernel, dim3 grid, dim3 block, unsigned smem, Args... args)
{
    cudaLaunchAttribute attr[1];
    attr[0].id = cudaLaunchAttributeProgrammaticStreamSerialization;
    attr[0].val.programmaticStreamSerializationAllowed = 1;
    cudaLaunchConfig_t cfg{};
    cfg.gridDim = grid;
    cfg.blockDim = block;
    cfg.dynamicSmemBytes = smem;
    cfg.stream = 0;
    cfg.attrs = attr;
    cfg.numAttrs = 1;
    cudaLaunchKernelEx(&cfg, kernel, args...);
}

extern "C" void kernel_launch(void* const* d_in, const int* in_sizes, int n_in,
                              void* d_out, int out_size)
{
    const float* x      = (const float*)d_in[0];
    const float* W_qkv  = (const float*)d_in[1];
    const float* b_qkv  = (const float*)d_in[2];
    const float* W_fc   = (const float*)d_in[3];
    const float* b_fc   = (const float*)d_in[4];
    const float* W_proj = (const float*)d_in[5];
    const float* b_proj = (const float*)d_in[6];
    float* out = (float*)d_out;

    float *p_qkv, *p_x1, *p_h;
    cudaGetSymbolAddress((void**)&p_qkv,  g_qkv);
    cudaGetSymbolAddress((void**)&p_x1,   g_x1);
    cudaGetSymbolAddress((void**)&p_h,    g_h);

    static bool cfgd = false;
    if (!cfgd) {
        cudaFuncSetAttribute(attn_kernel, cudaFuncAttributeMaxDynamicSharedMemorySize, ATTN_SMEM);
        cfgd = true;
    }

    // 1) qkv = x @ W_qkv + b_qkv            (1024 x 768, K=256) grid 192
    launch_pdl(gemm_tc<0, false, false, false>, dim3(12, 16), dim3(256), 0,
               x, W_qkv, b_qkv, (const float*)nullptr, p_qkv, NTOK, 3 * DM, DM, DM);

    // 2) x1 = x + attention(qkv); out seeded with x1 + b_proj
    launch_pdl(attn_kernel, dim3(128), dim3(512), ATTN_SMEM,
               x, p_qkv, b_proj, p_x1, out);

    // 3) h = quick_gelu(x1 @ W_fc + b_fc)   (1024 x 1024, K=256) grid 256
    launch_pdl(gemm_tc<1, false, false, true>, dim3(16, 16), dim3(256), 0,
               p_x1, W_fc, b_fc, (const float*)nullptr, p_h, NTOK, 4 * DM, DM, DM);

    // 4) out += h @ W_proj via vector REDG, split-K x8 (Ksplit=128) grid 512
    launch_pdl(gemm_tc<0, false, true, true>, dim3(4, 16, KSPLIT), dim3(256), 0,
               p_h, W_proj, (const float*)nullptr, (const float*)nullptr,
               out, NTOK, DM, 1024 / KSPLIT, 4 * DM);
}

// round 16
// speedup vs baseline: 1.0660x; 1.0016x over previous
#include <cuda_runtime.h>
#include <cuda_bf16.h>
#include <math.h>

// Shapes (fixed): B=2, T=512, D=256, H=8, c=32
#define NTOK 1024
#define DM   256
#define NH   8
#define HC   32
#define T    512
#define KSPLIT 8

__device__ float g_qkv [NTOK * 3 * DM];          // 1024 x 768
__device__ float g_x1  [NTOK * DM];              // 1024 x 256
__device__ float g_h   [NTOK * 4 * DM];          // 1024 x 1024

__device__ __forceinline__ void cp16(void* smem_dst, const void* gsrc) {
    unsigned s = (unsigned)__cvta_generic_to_shared(smem_dst);
    asm volatile("cp.async.cg.shared.global [%0], [%1], 16;\n" :: "r"(s), "l"(gsrc));
}

__device__ __forceinline__ void red2(float* gaddr, float v0, float v1) {
    asm volatile("red.global.add.v2.f32 [%0], {%1, %2};\n"
                 :: "l"(gaddr), "f"(v0), "f"(v1) : "memory");
}

// packed f32x2 helpers (sm_100+)
__device__ __forceinline__ unsigned long long addx2(unsigned long long a, unsigned long long b) {
    unsigned long long d;
    asm("add.rn.f32x2 %0, %1, %2;" : "=l"(d) : "l"(a), "l"(b));
    return d;
}
__device__ __forceinline__ void unpack2(unsigned long long v, float& lo, float& hi) {
    asm("mov.b64 {%0, %1}, %2;" : "=f"(lo), "=f"(hi) : "l"(v));
}

// ---------------------------------------------------------------------------
// TF32 tensor-core GEMM, STAGES-deep cp.async pipeline, split-K via blockIdx.z.
// BM=64, BN=64, BK=32, 256 threads, warp tile 32x16.
// STAGES=3 for short mainloops (nt=4), 4 for longer (nt=8).
// RED=true: epilogue red.global.v2 of bare partials into pre-seeded C.
// Requires nt >= STAGES - 1.
// ---------------------------------------------------------------------------
template<int ACT, bool RES, bool RED, bool DEP, int STAGES>
__global__ void gemm_tc(const float* __restrict__ A, const float* __restrict__ B,
                        const float* __restrict__ bias, const float* __restrict__ res,
                        float* __restrict__ C, int M, int N, int Klen, int lda)
{
    __shared__ float As[STAGES][64 * 36];
    __shared__ float Bs[STAGES][32 * 68];

    const int tid  = threadIdx.x;
    const int w    = tid >> 5;
    const int lane = tid & 31;
    const int g    = lane >> 2;
    const int tg   = lane & 3;
    const int warpM = w >> 2;
    const int warpN = w & 3;

    const int row0 = blockIdx.y * 64;
    const int col0 = blockIdx.x * 64;

    const int kz = blockIdx.z * Klen;
    A += kz;
    B += (size_t)kz * N;

    float acc[2][2][4] = {};

    auto loadA = [&](int k0, int buf) {
        #pragma unroll
        for (int c = tid; c < 512; c += 256) {
            int rA = c >> 3, cA = (c & 7) * 4;
            cp16(&As[buf][rA * 36 + cA], A + (size_t)(row0 + rA) * lda + k0 + cA);
        }
    };
    auto loadB = [&](int k0, int buf) {
        #pragma unroll
        for (int c = tid; c < 512; c += 256) {
            int rB = c >> 4, cB = (c & 15) * 4;
            cp16(&Bs[buf][rB * 68 + cB], B + (size_t)(k0 + rB) * N + col0 + cB);
        }
    };

    const int nt = Klen >> 5;   // >= STAGES-1 assumed
    constexpr int PRE = STAGES - 1;

    // Prologue: independent weight tiles first, then sync, then activations.
    #pragma unroll
    for (int s = 0; s < PRE; s++) loadB(s << 5, s);
    if (DEP) cudaGridDependencySynchronize();
    #pragma unroll
    for (int s = 0; s < PRE; s++) {
        loadA(s << 5, s);
        asm volatile("cp.async.commit_group;\n");
    }

    for (int i = 0; i < nt; i++) {
        if (i + PRE < nt) {
            loadB((i + PRE) << 5, (i + PRE) % STAGES);
            loadA((i + PRE) << 5, (i + PRE) % STAGES);
            asm volatile("cp.async.commit_group;\n");
            asm volatile("cp.async.wait_group %0;\n" :: "n"(PRE));
        } else if (i + 2 < nt && PRE >= 3) {
            asm volatile("cp.async.wait_group 2;\n");
        } else if (i + 1 < nt) {
            asm volatile("cp.async.wait_group 1;\n");
        } else {
            asm volatile("cp.async.wait_group 0;\n");
        }
        __syncthreads();

        const float* Ab = As[i % STAGES];
        const float* Bb = Bs[i % STAGES];

        #pragma unroll
        for (int ks = 0; ks < 4; ks++) {
            const int kk = ks * 8;
            unsigned a[2][4], b[2][2];
            #pragma unroll
            for (int ii = 0; ii < 2; ii++) {
                const int rb = warpM * 32 + ii * 16;
                a[ii][0] = __float_as_uint(Ab[(rb + g    ) * 36 + kk + tg    ]);
                a[ii][1] = __float_as_uint(Ab[(rb + g + 8) * 36 + kk + tg    ]);
                a[ii][2] = __float_as_uint(Ab[(rb + g    ) * 36 + kk + tg + 4]);
                a[ii][3] = __float_as_uint(Ab[(rb + g + 8) * 36 + kk + tg + 4]);
            }
            #pragma unroll
            for (int j = 0; j < 2; j++) {
                const int cb = warpN * 16 + j * 8;
                b[j][0] = __float_as_uint(Bb[(kk + tg    ) * 68 + cb + g]);
                b[j][1] = __float_as_uint(Bb[(kk + tg + 4) * 68 + cb + g]);
            }
            #pragma unroll
            for (int ii = 0; ii < 2; ii++)
                #pragma unroll
                for (int j = 0; j < 2; j++) {
                    asm volatile(
                        "mma.sync.aligned.m16n8k8.row.col.f32.tf32.tf32.f32 "
                        "{%0,%1,%2,%3}, {%4,%5,%6,%7}, {%8,%9}, {%0,%1,%2,%3};"
                        : "+f"(acc[ii][j][0]), "+f"(acc[ii][j][1]),
                          "+f"(acc[ii][j][2]), "+f"(acc[ii][j][3])
                        : "r"(a[ii][0]), "r"(a[ii][1]), "r"(a[ii][2]), "r"(a[ii][3]),
                          "r"(b[j][0]), "r"(b[j][1]));
                }
        }
        __syncthreads();
    }

    #pragma unroll
    for (int ii = 0; ii < 2; ii++) {
        const int rb = row0 + warpM * 32 + ii * 16;
        #pragma unroll
        for (int j = 0; j < 2; j++) {
            const int cb = col0 + warpN * 16 + j * 8;
            #pragma unroll
            for (int rg = 0; rg < 2; rg++) {
                const int r = rb + g + rg * 8;
                const int c = cb + tg * 2;
                float v0 = acc[ii][j][rg * 2 + 0];
                float v1 = acc[ii][j][rg * 2 + 1];
                if (RED) {
                    red2(&C[(size_t)r * N + c], v0, v1);   // vector REDG
                } else {
                    v0 += bias[c];
                    v1 += bias[c + 1];
                    if (ACT == 1) {
                        v0 = v0 * __fdividef(1.f, 1.f + __expf(-1.702f * v0));
                        v1 = v1 * __fdividef(1.f, 1.f + __expf(-1.702f * v1));
                    }
                    if (RES) {
                        float2 rv = *(const float2*)&res[(size_t)r * N + c];
                        v0 += rv.x; v1 += rv.y;
                    }
                    float2 o; o.x = v0; o.y = v1;
                    *(float2*)&C[(size_t)r * N + c] = o;
                }
            }
        }
    }
    cudaTriggerProgrammaticLaunchCompletion();   // after stores
}

// ---------------------------------------------------------------------------
// L1-distance attention + residual. 128 blocks x 512 threads (16 warps).
// Phase A: per chunk of 128 keys, warp w computes p for 16 keys x 32 queries,
// stores transposed P[key][query] (stride 72, conflict-free).
// Phase B: O[64x32] += P @ V_chunk on tensor cores, one m16n8 tile per warp.
// Epilogue writes x1 = x + attn AND seeds out = x1 + b_proj (proj REDs later).
// ---------------------------------------------------------------------------
#define ATTN_SMEM 186624
__global__ void attn_kernel(const float* __restrict__ x, const float* __restrict__ qkv,
                            const float* __restrict__ b_proj,
                            float* __restrict__ x1, float* __restrict__ outseed)
{
    extern __shared__ float sh[];
    float* Kneg = sh;                    // [512][32]  16384 floats
    float* Vsh  = sh + 16384;            // [512][40]  20480 floats
    float* Psh  = sh + 36864;            // [128][72]   9216 floats
    float* lbuf = sh + 46080;            // [64][8]
    float* Linv = sh + 46592;            // [64]

    const int bid = blockIdx.x;
    const int bh  = bid >> 3;
    const int qb  = bid & 7;
    const int b   = bh >> 3;
    const int hh  = bh & 7;
    const int tid = threadIdx.x;
    const int w   = tid >> 5;
    const int lane = tid & 31;
    const int t0  = qb * 64;

    const int qg = w & 1;
    const int ss = w >> 1;
    const int q  = qg * 32 + lane;
    const int t  = t0 + q;

    const int g  = lane >> 2;
    const int tg = lane & 3;
    const int mi = w >> 2;
    const int nj = w & 3;

    const float* qkv_bh = qkv + (size_t)b * T * 768 + hh * 96;

    cudaGridDependencySynchronize();     // qkv must be complete

    for (int i = tid; i < 4096; i += 512) {
        int s = i >> 3, j = i & 7;
        uint4 kv = *(const uint4*)(qkv_bh + (size_t)s * 768 + 32 + j * 4);
        kv.x ^= 0x80000000u; kv.y ^= 0x80000000u;
        kv.z ^= 0x80000000u; kv.w ^= 0x80000000u;
        *(uint4*)(Kneg + s * 32 + j * 4) = kv;
        *(float4*)(Vsh + s * 40 + j * 4) =
            *(const float4*)(qkv_bh + (size_t)s * 768 + 64 + j * 4);
    }

    unsigned long long q2[16];
    {
        const ulonglong2* qsrc = (const ulonglong2*)(qkv_bh + (size_t)t * 768);
        #pragma unroll
        for (int j = 0; j < 8; j++) {
            ulonglong2 v = qsrc[j];
            q2[2 * j] = v.x; q2[2 * j + 1] = v.y;
        }
    }
    __syncthreads();

    const float scale = 0.1767766952966369f;
    const unsigned long long ABSM = 0x7FFFFFFF7FFFFFFFULL;
    float l = 0.f;
    float acc[4] = {};

    #pragma unroll 1
    for (int ch = 0; ch < 4; ch++) {
        #pragma unroll 2
        for (int i2 = 0; i2 < 16; i2++) {
            const int kc = ss * 16 + i2;
            const int sg = ch * 128 + kc;
            const ulonglong2* krow = (const ulonglong2*)(Kneg + sg * 32);
            unsigned long long accA = 0ULL, accB = 0ULL;
            #pragma unroll
            for (int j = 0; j < 8; j++) {
                ulonglong2 kk = krow[j];
                unsigned long long d0 = addx2(q2[2 * j],     kk.x) & ABSM;
                unsigned long long d1 = addx2(q2[2 * j + 1], kk.y) & ABSM;
                accA = addx2(accA, d0);
                accB = addx2(accB, d1);
            }
            float a0, a1, b0, b1;
            unpack2(accA, a0, a1);
            unpack2(accB, b0, b1);
            float dist = (a0 + a1) + (b0 + b1);
            float wgt = (sg == t) ? 0.f : __fdividef(1.f, 0.001f + dist * scale);
            float p = __expf(wgt);
            l += p;
            Psh[kc * 72 + q] = p;
        }
        __syncthreads();

        const float* Vch = Vsh + ch * 128 * 40;
        #pragma unroll
        for (int ks = 0; ks < 16; ks++) {
            const int kk = ks * 8;
            unsigned a0 = __float_as_uint(Psh[(kk + tg    ) * 72 + mi * 16 + g    ]);
            unsigned a1 = __float_as_uint(Psh[(kk + tg    ) * 72 + mi * 16 + g + 8]);
            unsigned a2 = __float_as_uint(Psh[(kk + tg + 4) * 72 + mi * 16 + g    ]);
            unsigned a3 = __float_as_uint(Psh[(kk + tg + 4) * 72 + mi * 16 + g + 8]);
            unsigned b0 = __float_as_uint(Vch[(kk + tg    ) * 40 + nj * 8 + g]);
            unsigned b1 = __float_as_uint(Vch[(kk + tg + 4) * 40 + nj * 8 + g]);
            asm volatile(
                "mma.sync.aligned.m16n8k8.row.col.f32.tf32.tf32.f32 "
                "{%0,%1,%2,%3}, {%4,%5,%6,%7}, {%8,%9}, {%0,%1,%2,%3};"
                : "+f"(acc[0]), "+f"(acc[1]), "+f"(acc[2]), "+f"(acc[3])
                : "r"(a0), "r"(a1), "r"(a2), "r"(a3), "r"(b0), "r"(b1));
        }
        __syncthreads();
    }

    lbuf[q * 8 + ss] = l;
    __syncthreads();
    if (tid < 64) {
        float L = 0.f;
        #pragma unroll
        for (int i = 0; i < 8; i++) L += lbuf[tid * 8 + i];
        Linv[tid] = __fdividef(1.f, L);
    }
    __syncthreads();

    // Epilogue: x1 = x + attn ; outseed = x1 + b_proj (proj REDs on top)
    {
        const int c0 = nj * 8 + tg * 2;
        float2 bp = *(const float2*)&b_proj[hh * HC + c0];
        #pragma unroll
        for (int rg = 0; rg < 2; rg++) {
            const int r = mi * 16 + g + rg * 8;
            float inv = Linv[r];
            size_t idx = ((size_t)b * T + (t0 + r)) * DM + hh * HC + c0;
            float2 xv = *(const float2*)&x[idx];
            float2 o;
            o.x = xv.x + acc[rg * 2 + 0] * inv;
            o.y = xv.y + acc[rg * 2 + 1] * inv;
            *(float2*)&x1[idx] = o;
            float2 osd; osd.x = o.x + bp.x; osd.y = o.y + bp.y;
            *(float2*)&outseed[idx] = osd;
        }
    }
    cudaTriggerProgrammaticLaunchCompletion();   // after stores
}

// ---------------------------------------------------------------------------
template<typename K, typename... Args>
static void launch_pdl(K kernel, dim3 grid, dim3 block, unsigned smem, Args... args)
{
    cudaLaunchAttribute attr[1];
    attr[0].id = cudaLaunchAttributeProgrammaticStreamSerialization;
    attr[0].val.programmaticStreamSerializationAllowed = 1;
    cudaLaunchConfig_t cfg{};
    cfg.gridDim = grid;
    cfg.blockDim = block;
    cfg.dynamicSmemBytes = smem;
    cfg.stream = 0;
    cfg.attrs = attr;
    cfg.numAttrs = 1;
    cudaLaunchKernelEx(&cfg, kernel, args...);
}

extern "C" void kernel_launch(void* const* d_in, const int* in_sizes, int n_in,
                              void* d_out, int out_size)
{
    const float* x      = (const float*)d_in[0];
    const float* W_qkv  = (const float*)d_in[1];
    const float* b_qkv  = (const float*)d_in[2];
    const float* W_fc   = (const float*)d_in[3];
    const float* b_fc   = (const float*)d_in[4];
    const float* W_proj = (const float*)d_in[5];
    const float* b_proj = (const float*)d_in[6];
    float* out = (float*)d_out;

    float *p_qkv, *p_x1, *p_h;
    cudaGetSymbolAddress((void**)&p_qkv,  g_qkv);
    cudaGetSymbolAddress((void**)&p_x1,   g_x1);
    cudaGetSymbolAddress((void**)&p_h,    g_h);

    static bool cfgd = false;
    if (!cfgd) {
        cudaFuncSetAttribute(attn_kernel, cudaFuncAttributeMaxDynamicSharedMemorySize, ATTN_SMEM);
        cfgd = true;
    }

    // 1) qkv = x @ W_qkv + b_qkv            (1024 x 768, K=256, nt=8) 4-stage
    launch_pdl(gemm_tc<0, false, false, false, 4>, dim3(12, 16), dim3(256), 0,
               x, W_qkv, b_qkv, (const float*)nullptr, p_qkv, NTOK, 3 * DM, DM, DM);

    // 2) x1 = x + attention(qkv); out seeded with x1 + b_proj
    launch_pdl(attn_kernel, dim3(128), dim3(512), ATTN_SMEM,
               x, p_qkv, b_proj, p_x1, out);

    // 3) h = quick_gelu(x1 @ W_fc + b_fc)   (1024 x 1024, K=256, nt=8) 4-stage
    launch_pdl(gemm_tc<1, false, false, true, 4>, dim3(16, 16), dim3(256), 0,
               p_x1, W_fc, b_fc, (const float*)nullptr, p_h, NTOK, 4 * DM, DM, DM);

    // 4) out += h @ W_proj via vector REDG, split-K x8 (nt=4) 3-stage
    launch_pdl(gemm_tc<0, false, true, true, 3>, dim3(4, 16, KSPLIT), dim3(256), 0,
               p_h, W_proj, (const float*)nullptr, (const float*)nullptr,
               out, NTOK, DM, 1024 / KSPLIT, 4 * DM);
}